// round 6
// baseline (speedup 1.0000x reference)
#include <cuda_runtime.h>

#define R     5
#define TILE  32
#define HT    42          // TILE + 2*R
#define NIMG  48          // 16 batch * 3 channels (depthwise -> independent planes)

// Normalized 11-tap Gaussian (sigma=1.5) as compile-time literals
__device__ __forceinline__ float gw(int t) {
    constexpr float W[11] = {
        0.00102838f, 0.00759876f, 0.03600075f, 0.10936071f, 0.21300558f,
        0.26601173f,
        0.21300558f, 0.10936071f, 0.03600075f, 0.00759876f, 0.00102838f
    };
    return W[t];
}

// Pyramid in (s,d) space: s=x+y, d=x-y, interleaved float2.
__device__ float2 g_pyrA[NIMG * 256 * 256];   // level 1
__device__ float2 g_pyrB[NIMG * 128 * 128];   // level 2
__device__ float2 g_pyrC[NIMG * 64 * 64];     // level 3
__device__ float2 g_pyrD[NIMG * 32 * 32];     // level 4
__device__ double g_acc[5];

__global__ void zero_acc_kernel() {
    if (threadIdx.x < 5) g_acc[threadIdx.x] = 0.0;
}

// One 32x32 SSIM tile in (s,d) space.
// Pass 1: vertical blur of {s, d, s^2, d^2}, 8-row units (2.25 reads/elt).
// Pass 2: horizontal blur, 8-px units via 9 x LDS.128/stream, SSIM, reduce.
template<bool POOL, bool SD_IN>
__device__ __forceinline__ void ssim_tile(
    const float* __restrict__ X, const float* __restrict__ Y,   // SD_IN=false
    const float2* __restrict__ XY,                              // SD_IN=true
    int H, int W, int tx, int ty, int img,
    double* __restrict__ acc, float2* __restrict__ PO)
{
    __shared__ __align__(16) float2 sxy[HT][43];     // (s, d)
    __shared__ __align__(16) float2 hbSD[TILE][44];  // v-blurred (s, d)
    __shared__ __align__(16) float2 hbPQ[TILE][44];  // v-blurred (s^2, d^2)
    __shared__ float wsum[8];

    const int tid  = threadIdx.x;
    const int base = img * H * W;
    const int r0   = ty * TILE - R;
    const int c0   = tx * TILE - R;

    // ---- load tile + halo (zero padding outside image) ----
    for (int i = tid; i < HT * HT; i += 256) {
        int r  = i / HT, c = i - r * HT;
        int gr = r0 + r, gc = c0 + c;
        float sv = 0.0f, dv = 0.0f;
        if ((unsigned)gr < (unsigned)H && (unsigned)gc < (unsigned)W) {
            int gi = base + gr * W + gc;
            if (SD_IN) {
                float2 v = XY[gi];
                sv = v.x; dv = v.y;
            } else {
                float xv = X[gi], yv = Y[gi];
                sv = xv + yv; dv = xv - yv;
            }
        }
        sxy[r][c] = make_float2(sv, dv);
    }
    __syncthreads();

    // ---- fused 2x2 avg-pool of the central 32x32 (next level's input) ----
    if (POOL) {
        int pr = tid >> 4, pc = tid & 15;
        int rr = R + 2 * pr, cc = R + 2 * pc;
        float2 a = sxy[rr][cc],     b = sxy[rr][cc + 1];
        float2 c = sxy[rr + 1][cc], d = sxy[rr + 1][cc + 1];
        int Ho = H >> 1, Wo = W >> 1;
        int o  = img * Ho * Wo + (ty * 16 + pr) * Wo + tx * 16 + pc;
        PO[o] = make_float2(0.25f * (a.x + b.x + c.x + d.x),
                            0.25f * (a.y + b.y + c.y + d.y));
    }

    // ---- pass 1: vertical blur, 8 output rows per unit (168 units) ----
    if (tid < HT * 4) {
        int c  = tid % HT;
        int rb = (tid / HT) * 8;
        float aS[8] = {}, aD[8] = {}, aP[8] = {}, aQ[8] = {};
#pragma unroll
        for (int t = 0; t < 18; t++) {
            float2 v = sxy[rb + t][c];
            float s2 = v.x * v.x, d2 = v.y * v.y;
#pragma unroll
            for (int k = 0; k < 8; k++) {
                int tt = t - k;                 // compile-time after unroll
                if (tt >= 0 && tt <= 10) {
                    float w = gw(tt);
                    aS[k] += w * v.x;
                    aD[k] += w * v.y;
                    aP[k] += w * s2;
                    aQ[k] += w * d2;
                }
            }
        }
#pragma unroll
        for (int k = 0; k < 8; k++) {
            hbSD[rb + k][c] = make_float2(aS[k], aD[k]);
            hbPQ[rb + k][c] = make_float2(aP[k], aQ[k]);
        }
    }
    __syncthreads();

    // ---- pass 2: horizontal blur + SSIM, 8 px/thread (128 units) ----
    float lsum = 0.f;
    if (tid < 128) {
        const int vr  = tid >> 2;         // output row 0..31
        const int vc0 = (tid & 3) * 8;    // output col group base

        float mS[8] = {}, mD[8] = {}, mP[8] = {}, mQ[8] = {};

        {   // (S, D) stream — 9 x LDS.128 covering 18 float2
            const float4* p = (const float4*)&hbSD[vr][vc0];
#pragma unroll
            for (int q = 0; q < 9; q++) {
                float4 a = p[q];
#pragma unroll
                for (int k = 0; k < 8; k++) {
                    int t0 = 2 * q - k, t1 = 2 * q + 1 - k;
                    if (t0 >= 0 && t0 <= 10) { mS[k] += gw(t0) * a.x; mD[k] += gw(t0) * a.y; }
                    if (t1 >= 0 && t1 <= 10) { mS[k] += gw(t1) * a.z; mD[k] += gw(t1) * a.w; }
                }
            }
        }
        {   // (P, Q) stream — 9 x LDS.128
            const float4* p = (const float4*)&hbPQ[vr][vc0];
#pragma unroll
            for (int q = 0; q < 9; q++) {
                float4 a = p[q];
#pragma unroll
                for (int k = 0; k < 8; k++) {
                    int t0 = 2 * q - k, t1 = 2 * q + 1 - k;
                    if (t0 >= 0 && t0 <= 10) { mP[k] += gw(t0) * a.x; mQ[k] += gw(t0) * a.y; }
                    if (t1 >= 0 && t1 <= 10) { mP[k] += gw(t1) * a.z; mQ[k] += gw(t1) * a.w; }
                }
            }
        }

        const float C1 = 4.0e-4f;   // (0.01*2)^2
        const float C2 = 3.6e-3f;   // (0.03*2)^2
#pragma unroll
        for (int k = 0; k < 8; k++) {
            float S2 = mS[k] * mS[k];
            float D2 = mD[k] * mD[k];
            float sumSq = 0.5f * (S2 + D2);                   // mu1^2 + mu2^2
            float difSq = 0.5f * (S2 - D2);                   // 2*mu1*mu2
            float A1 = difSq + C1;
            float B1 = sumSq + C1;
            float A2 = 0.5f * (mP[k] - mQ[k]) - difSq + C2;   // 2*sig12 + C2
            float B2 = 0.5f * (mP[k] + mQ[k]) - sumSq + C2;   // sig1+sig2 + C2
            lsum += __fdividef(A1 * A2, B1 * B2 + 1e-8f);
        }
    }

    // ---- block reduction -> one double atomic per block ----
#pragma unroll
    for (int o = 16; o > 0; o >>= 1)
        lsum += __shfl_xor_sync(0xFFFFFFFFu, lsum, o);
    if ((tid & 31) == 0) wsum[tid >> 5] = lsum;
    __syncthreads();
    if (tid == 0) {
        float b = 0.f;
#pragma unroll
        for (int i = 0; i < 8; i++) b += wsum[i];
        atomicAdd(acc, (double)b);
    }
}

// Level 0 (512^2), fused pool -> pyrA (256^2, s/d space)
__global__ __launch_bounds__(256, 4) void ssim_l0_kernel(
    const float* __restrict__ X, const float* __restrict__ Y,
    double* __restrict__ acc, float2* __restrict__ PO)
{
    ssim_tile<true, false>(X, Y, nullptr, 512, 512,
                           blockIdx.x, blockIdx.y, blockIdx.z, acc, PO);
}

// Merged tail: all 85 tiles/image of levels 1..4 in one launch.
__global__ __launch_bounds__(256, 4) void ssim_tail_kernel(
    const float2* __restrict__ A, const float2* __restrict__ B,
    const float2* __restrict__ C, const float2* __restrict__ D,
    double* __restrict__ acc)
{
    int bx = blockIdx.x;
    const float2* XY;
    int H, tx, ty, lvl;
    if (bx < 64)      { lvl = 1; H = 256; tx = bx & 7;  ty = bx >> 3;               XY = A; }
    else if (bx < 80) { lvl = 2; H = 128; int b = bx - 64; tx = b & 3; ty = b >> 2; XY = B; }
    else if (bx < 84) { lvl = 3; H = 64;  int b = bx - 80; tx = b & 1; ty = b >> 1; XY = C; }
    else              { lvl = 4; H = 32;  tx = 0; ty = 0;                           XY = D; }
    ssim_tile<false, true>(nullptr, nullptr, XY, H, H, tx, ty, blockIdx.z,
                           acc + lvl, nullptr);
}

// Local pyramid: each block pools its 64x64 region of A (256^2) down to
// B (128^2), C (64^2), D (32^2) entirely in smem. grid (4,4,NIMG).
__global__ __launch_bounds__(256) void pooltree_kernel(
    const float2* __restrict__ A, float2* __restrict__ B,
    float2* __restrict__ C, float2* __restrict__ D)
{
    __shared__ float2 p1[32][33];
    __shared__ float2 p2[16][17];
    const int tid = threadIdx.x;
    const int img = blockIdx.z;
    const int rx  = blockIdx.x, ry = blockIdx.y;

    const float2* a0 = A + img * 256 * 256;

    // pool A(64x64 region) -> 32x32, 4 outputs/thread
#pragma unroll
    for (int j = 0; j < 4; j++) {
        int o = tid + j * 256;            // 0..1023
        int r = o >> 5, c = o & 31;
        int gr = ry * 64 + 2 * r, gc = rx * 64 + 2 * c;
        float2 a = a0[gr * 256 + gc],       b = a0[gr * 256 + gc + 1];
        float2 e = a0[(gr + 1) * 256 + gc], f = a0[(gr + 1) * 256 + gc + 1];
        float2 pv = make_float2(0.25f * (a.x + b.x + e.x + f.x),
                                0.25f * (a.y + b.y + e.y + f.y));
        int ob = img * 128 * 128 + (ry * 32 + r) * 128 + rx * 32 + c;
        B[ob] = pv;
        p1[r][c] = pv;
    }
    __syncthreads();

    // 32x32 -> 16x16, 1 output/thread
    {
        int r = tid >> 4, c = tid & 15;
        float2 a = p1[2 * r][2 * c],     b = p1[2 * r][2 * c + 1];
        float2 d = p1[2 * r + 1][2 * c], e = p1[2 * r + 1][2 * c + 1];
        float2 pv = make_float2(0.25f * (a.x + b.x + d.x + e.x),
                                0.25f * (a.y + b.y + d.y + e.y));
        int oc = img * 64 * 64 + (ry * 16 + r) * 64 + rx * 16 + c;
        C[oc] = pv;
        p2[r][c] = pv;
    }
    __syncthreads();

    // 16x16 -> 8x8
    if (tid < 64) {
        int r = tid >> 3, c = tid & 7;
        float2 a = p2[2 * r][2 * c],     b = p2[2 * r][2 * c + 1];
        float2 d = p2[2 * r + 1][2 * c], e = p2[2 * r + 1][2 * c + 1];
        int od = img * 32 * 32 + (ry * 8 + r) * 32 + rx * 8 + c;
        D[od] = make_float2(0.25f * (a.x + b.x + d.x + e.x),
                            0.25f * (a.y + b.y + d.y + e.y));
    }
}

__global__ void finish_kernel(float* __restrict__ out) {
    const double w[5] = {0.0448, 0.2856, 0.3001, 0.2363, 0.1333};
    const double wsumv = 1.0001;  // reference normalizes by the weight sum
    double cnt = (double)NIMG * 512.0 * 512.0;
    double m = 0.0;
#pragma unroll
    for (int l = 0; l < 5; l++) {
        m += (w[l] / wsumv) * (g_acc[l] / cnt);
        cnt *= 0.25;
    }
    out[0] = (float)(1.0 - m);
}

extern "C" void kernel_launch(void* const* d_in, const int* in_sizes, int n_in,
                              void* d_out, int out_size)
{
    (void)in_sizes; (void)n_in; (void)out_size;
    const float* pred   = (const float*)d_in[0];
    const float* target = (const float*)d_in[1];
    float* out = (float*)d_out;

    float2 *pA, *pB, *pC, *pD;
    double* acc;
    cudaGetSymbolAddress((void**)&pA, g_pyrA);
    cudaGetSymbolAddress((void**)&pB, g_pyrB);
    cudaGetSymbolAddress((void**)&pC, g_pyrC);
    cudaGetSymbolAddress((void**)&pD, g_pyrD);
    cudaGetSymbolAddress((void**)&acc, g_acc);

    zero_acc_kernel<<<1, 32>>>();

    // L0: SSIM + fused pool -> A (256^2, s/d space)
    ssim_l0_kernel<<<dim3(16, 16, NIMG), 256>>>(pred, target, acc, pA);

    // Build remaining pyramid locally: A -> B, C, D
    pooltree_kernel<<<dim3(4, 4, NIMG), 256>>>(pA, pB, pC, pD);

    // Levels 1..4 merged into a single launch (85 tiles per image)
    ssim_tail_kernel<<<dim3(85, 1, NIMG), 256>>>(pA, pB, pC, pD, acc);

    finish_kernel<<<1, 1>>>(out);
}

// round 7
// speedup vs baseline: 1.0777x; 1.0777x over previous
#include <cuda_runtime.h>

#define R     5
#define TILE  32
#define HT    42          // TILE + 2*R
#define NIMG  48          // 16 batch * 3 channels (depthwise -> independent planes)

typedef unsigned long long ull;

// Normalized 11-tap Gaussian (sigma=1.5) as compile-time literals
__device__ __forceinline__ float gw(int t) {
    constexpr float W[11] = {
        0.00102838f, 0.00759876f, 0.03600075f, 0.10936071f, 0.21300558f,
        0.26601173f,
        0.21300558f, 0.10936071f, 0.03600075f, 0.00759876f, 0.00102838f
    };
    return W[t];
}

// ---- f32x2 packed helpers (sm_100+) ----
__device__ __forceinline__ ull pk2(float a, float b) {
    ull r; asm("mov.b64 %0, {%1,%2};" : "=l"(r) : "f"(a), "f"(b)); return r;
}
__device__ __forceinline__ float2 upk2(ull v) {
    float2 r; asm("mov.b64 {%0,%1}, %2;" : "=f"(r.x), "=f"(r.y) : "l"(v)); return r;
}
__device__ __forceinline__ ull fma2(ull a, ull b, ull c) {
    ull d; asm("fma.rn.f32x2 %0, %1, %2, %3;" : "=l"(d) : "l"(a), "l"(b), "l"(c)); return d;
}
__device__ __forceinline__ ull mul2(ull a, ull b) {
    ull d; asm("mul.rn.f32x2 %0, %1, %2;" : "=l"(d) : "l"(a), "l"(b)); return d;
}
__device__ __forceinline__ ull wp(int t) { return pk2(gw(t), gw(t)); }

// Pyramid in (s,d) space: s=x+y, d=x-y, interleaved float2.
__device__ float2 g_pyrA[NIMG * 256 * 256];   // level 1
__device__ float2 g_pyrB[NIMG * 128 * 128];   // level 2
__device__ float2 g_pyrC[NIMG * 64 * 64];     // level 3
__device__ float2 g_pyrD[NIMG * 32 * 32];     // level 4
__device__ double g_acc[5];

__global__ void zero_acc_kernel() {
    if (threadIdx.x < 5) g_acc[threadIdx.x] = 0.0;
}

// One 32x32 SSIM tile in (s,d) space. R5 structure (balanced threads) with
// f32x2 packed conv math on the (S,D)/(P,Q) pairs.
// Pass 1: vertical blur of {s, d, s^2, d^2}, 4-row units, 336 units/256 thr.
// Pass 2: horizontal blur via LDS.128, 4 px/thread, packed fma2; SSIM; reduce.
template<bool POOL, bool SD_IN>
__device__ __forceinline__ void ssim_tile(
    const float* __restrict__ X, const float* __restrict__ Y,   // SD_IN=false
    const float2* __restrict__ XY,                              // SD_IN=true
    int H, int W, int tx, int ty, int img,
    double* __restrict__ acc, float2* __restrict__ PO)
{
    __shared__ __align__(16) float2 sxy[HT][43];     // (s, d)
    __shared__ __align__(16) float2 hbSD[TILE][44];  // v-blurred (s, d)
    __shared__ __align__(16) float2 hbPQ[TILE][44];  // v-blurred (s^2, d^2)
    __shared__ float wsum[8];

    const int tid  = threadIdx.x;
    const int base = img * H * W;
    const int r0   = ty * TILE - R;
    const int c0   = tx * TILE - R;

    // ---- load tile + halo (zero padding outside image) ----
    for (int i = tid; i < HT * HT; i += 256) {
        int r  = i / HT, c = i - r * HT;
        int gr = r0 + r, gc = c0 + c;
        float sv = 0.0f, dv = 0.0f;
        if ((unsigned)gr < (unsigned)H && (unsigned)gc < (unsigned)W) {
            int gi = base + gr * W + gc;
            if (SD_IN) {
                float2 v = XY[gi];
                sv = v.x; dv = v.y;
            } else {
                float xv = X[gi], yv = Y[gi];
                sv = xv + yv; dv = xv - yv;
            }
        }
        sxy[r][c] = make_float2(sv, dv);
    }
    __syncthreads();

    // ---- fused 2x2 avg-pool of the central 32x32 (next level's input) ----
    if (POOL) {
        int pr = tid >> 4, pc = tid & 15;
        int rr = R + 2 * pr, cc = R + 2 * pc;
        float2 a = sxy[rr][cc],     b = sxy[rr][cc + 1];
        float2 c = sxy[rr + 1][cc], d = sxy[rr + 1][cc + 1];
        int Ho = H >> 1, Wo = W >> 1;
        int o  = img * Ho * Wo + (ty * 16 + pr) * Wo + tx * 16 + pc;
        PO[o] = make_float2(0.25f * (a.x + b.x + c.x + d.x),
                            0.25f * (a.y + b.y + c.y + d.y));
    }

    // ---- pass 1: vertical blur, 4 output rows per unit (336 units) ----
    for (int u = tid; u < HT * 8; u += 256) {
        int c  = u % HT;
        int rb = (u / HT) * 4;
        ull aSD[4] = {0, 0, 0, 0};
        ull aPQ[4] = {0, 0, 0, 0};
#pragma unroll
        for (int t = 0; t < 14; t++) {
            ull v  = *(const ull*)&sxy[rb + t][c];
            ull v2 = mul2(v, v);
#pragma unroll
            for (int k = 0; k < 4; k++) {
                int tt = t - k;                 // compile-time after unroll
                if (tt >= 0 && tt <= 10) {
                    aSD[k] = fma2(wp(tt), v,  aSD[k]);
                    aPQ[k] = fma2(wp(tt), v2, aPQ[k]);
                }
            }
        }
#pragma unroll
        for (int k = 0; k < 4; k++) {
            *(ull*)&hbSD[rb + k][c] = aSD[k];
            *(ull*)&hbPQ[rb + k][c] = aPQ[k];
        }
    }
    __syncthreads();

    // ---- pass 2: horizontal blur + SSIM, 4 px/thread ----
    const int vr = tid >> 3;          // output row 0..31
    const int vc = (tid & 7) * 4;     // output col group (16B aligned)

    ull accSD[4] = {0, 0, 0, 0};
    ull accPQ[4] = {0, 0, 0, 0};

    {   // (S, D) stream — 7 x LDS.128 (each = 2 packed taps)
        ull v[14];
        const ulonglong2* p = (const ulonglong2*)&hbSD[vr][vc];
#pragma unroll
        for (int q = 0; q < 7; q++) {
            ulonglong2 a = p[q];
            v[2 * q] = a.x; v[2 * q + 1] = a.y;
        }
#pragma unroll
        for (int t = 0; t < 14; t++)
#pragma unroll
            for (int k = 0; k < 4; k++) {
                int tt = t - k;
                if (tt >= 0 && tt <= 10) accSD[k] = fma2(wp(tt), v[t], accSD[k]);
            }
    }
    {   // (P, Q) stream — 7 x LDS.128
        ull v[14];
        const ulonglong2* p = (const ulonglong2*)&hbPQ[vr][vc];
#pragma unroll
        for (int q = 0; q < 7; q++) {
            ulonglong2 a = p[q];
            v[2 * q] = a.x; v[2 * q + 1] = a.y;
        }
#pragma unroll
        for (int t = 0; t < 14; t++)
#pragma unroll
            for (int k = 0; k < 4; k++) {
                int tt = t - k;
                if (tt >= 0 && tt <= 10) accPQ[k] = fma2(wp(tt), v[t], accPQ[k]);
            }
    }

    const float C1 = 4.0e-4f;   // (0.01*2)^2
    const float C2 = 3.6e-3f;   // (0.03*2)^2
    float lsum = 0.f;
#pragma unroll
    for (int k = 0; k < 4; k++) {
        float2 sd = upk2(accSD[k]);
        float2 pq = upk2(accPQ[k]);
        float S2 = sd.x * sd.x;
        float D2 = sd.y * sd.y;
        float sumSq = 0.5f * (S2 + D2);                 // mu1^2 + mu2^2
        float difSq = 0.5f * (S2 - D2);                 // 2*mu1*mu2
        float A1 = difSq + C1;
        float B1 = sumSq + C1;
        float A2 = 0.5f * (pq.x - pq.y) - difSq + C2;   // 2*sig12 + C2
        float B2 = 0.5f * (pq.x + pq.y) - sumSq + C2;   // sig1+sig2 + C2
        lsum += __fdividef(A1 * A2, B1 * B2 + 1e-8f);
    }

    // ---- block reduction -> one double atomic per block ----
#pragma unroll
    for (int o = 16; o > 0; o >>= 1)
        lsum += __shfl_xor_sync(0xFFFFFFFFu, lsum, o);
    if ((tid & 31) == 0) wsum[tid >> 5] = lsum;
    __syncthreads();
    if (tid == 0) {
        float b = 0.f;
#pragma unroll
        for (int i = 0; i < 8; i++) b += wsum[i];
        atomicAdd(acc, (double)b);
    }
}

// Level 0 (512^2), fused pool -> pyrA (256^2, s/d space)
__global__ __launch_bounds__(256, 5) void ssim_l0_kernel(
    const float* __restrict__ X, const float* __restrict__ Y,
    double* __restrict__ acc, float2* __restrict__ PO)
{
    ssim_tile<true, false>(X, Y, nullptr, 512, 512,
                           blockIdx.x, blockIdx.y, blockIdx.z, acc, PO);
}

// Merged tail: all 85 tiles/image of levels 1..4 in one launch.
__global__ __launch_bounds__(256, 5) void ssim_tail_kernel(
    const float2* __restrict__ A, const float2* __restrict__ B,
    const float2* __restrict__ C, const float2* __restrict__ D,
    double* __restrict__ acc)
{
    int bx = blockIdx.x;
    const float2* XY;
    int H, tx, ty, lvl;
    if (bx < 64)      { lvl = 1; H = 256; tx = bx & 7;  ty = bx >> 3;               XY = A; }
    else if (bx < 80) { lvl = 2; H = 128; int b = bx - 64; tx = b & 3; ty = b >> 2; XY = B; }
    else if (bx < 84) { lvl = 3; H = 64;  int b = bx - 80; tx = b & 1; ty = b >> 1; XY = C; }
    else              { lvl = 4; H = 32;  tx = 0; ty = 0;                           XY = D; }
    ssim_tile<false, true>(nullptr, nullptr, XY, H, H, tx, ty, blockIdx.z,
                           acc + lvl, nullptr);
}

// Local pyramid: each block pools its 64x64 region of A (256^2) down to
// B (128^2), C (64^2), D (32^2) entirely in smem. grid (4,4,NIMG).
__global__ __launch_bounds__(256) void pooltree_kernel(
    const float2* __restrict__ A, float2* __restrict__ B,
    float2* __restrict__ C, float2* __restrict__ D)
{
    __shared__ float2 p1[32][33];
    __shared__ float2 p2[16][17];
    const int tid = threadIdx.x;
    const int img = blockIdx.z;
    const int rx  = blockIdx.x, ry = blockIdx.y;

    const float2* a0 = A + img * 256 * 256;

    // pool A(64x64 region) -> 32x32, 4 outputs/thread
#pragma unroll
    for (int j = 0; j < 4; j++) {
        int o = tid + j * 256;            // 0..1023
        int r = o >> 5, c = o & 31;
        int gr = ry * 64 + 2 * r, gc = rx * 64 + 2 * c;
        float2 a = a0[gr * 256 + gc],       b = a0[gr * 256 + gc + 1];
        float2 e = a0[(gr + 1) * 256 + gc], f = a0[(gr + 1) * 256 + gc + 1];
        float2 pv = make_float2(0.25f * (a.x + b.x + e.x + f.x),
                                0.25f * (a.y + b.y + e.y + f.y));
        int ob = img * 128 * 128 + (ry * 32 + r) * 128 + rx * 32 + c;
        B[ob] = pv;
        p1[r][c] = pv;
    }
    __syncthreads();

    // 32x32 -> 16x16, 1 output/thread
    {
        int r = tid >> 4, c = tid & 15;
        float2 a = p1[2 * r][2 * c],     b = p1[2 * r][2 * c + 1];
        float2 d = p1[2 * r + 1][2 * c], e = p1[2 * r + 1][2 * c + 1];
        float2 pv = make_float2(0.25f * (a.x + b.x + d.x + e.x),
                                0.25f * (a.y + b.y + d.y + e.y));
        int oc = img * 64 * 64 + (ry * 16 + r) * 64 + rx * 16 + c;
        C[oc] = pv;
        p2[r][c] = pv;
    }
    __syncthreads();

    // 16x16 -> 8x8
    if (tid < 64) {
        int r = tid >> 3, c = tid & 7;
        float2 a = p2[2 * r][2 * c],     b = p2[2 * r][2 * c + 1];
        float2 d = p2[2 * r + 1][2 * c], e = p2[2 * r + 1][2 * c + 1];
        int od = img * 32 * 32 + (ry * 8 + r) * 32 + rx * 8 + c;
        D[od] = make_float2(0.25f * (a.x + b.x + d.x + e.x),
                            0.25f * (a.y + b.y + d.y + e.y));
    }
}

__global__ void finish_kernel(float* __restrict__ out) {
    const double w[5] = {0.0448, 0.2856, 0.3001, 0.2363, 0.1333};
    const double wsumv = 1.0001;  // reference normalizes by the weight sum
    double cnt = (double)NIMG * 512.0 * 512.0;
    double m = 0.0;
#pragma unroll
    for (int l = 0; l < 5; l++) {
        m += (w[l] / wsumv) * (g_acc[l] / cnt);
        cnt *= 0.25;
    }
    out[0] = (float)(1.0 - m);
}

extern "C" void kernel_launch(void* const* d_in, const int* in_sizes, int n_in,
                              void* d_out, int out_size)
{
    (void)in_sizes; (void)n_in; (void)out_size;
    const float* pred   = (const float*)d_in[0];
    const float* target = (const float*)d_in[1];
    float* out = (float*)d_out;

    float2 *pA, *pB, *pC, *pD;
    double* acc;
    cudaGetSymbolAddress((void**)&pA, g_pyrA);
    cudaGetSymbolAddress((void**)&pB, g_pyrB);
    cudaGetSymbolAddress((void**)&pC, g_pyrC);
    cudaGetSymbolAddress((void**)&pD, g_pyrD);
    cudaGetSymbolAddress((void**)&acc, g_acc);

    zero_acc_kernel<<<1, 32>>>();

    // L0: SSIM + fused pool -> A (256^2, s/d space)
    ssim_l0_kernel<<<dim3(16, 16, NIMG), 256>>>(pred, target, acc, pA);

    // Build remaining pyramid locally: A -> B, C, D
    pooltree_kernel<<<dim3(4, 4, NIMG), 256>>>(pA, pB, pC, pD);

    // Levels 1..4 merged into a single launch (85 tiles per image)
    ssim_tail_kernel<<<dim3(85, 1, NIMG), 256>>>(pA, pB, pC, pD, acc);

    finish_kernel<<<1, 1>>>(out);
}

// round 8
// speedup vs baseline: 1.0965x; 1.0175x over previous
#include <cuda_runtime.h>

#define R    5
#define TR   32          // tile rows
#define TC   64          // tile cols
#define HTR  42          // TR + 2R
#define HTC  74          // TC + 2R
#define SXP  76          // padded row stride (float2 units, 16B-aligned rows)
#define NIMG 48          // 16 batch * 3 channels

#define SMEM_BYTES ((42 + 32 + 32) * 76 * 8 + 64)   // sxy + hbSD + hbPQ + wsum

// Normalized 11-tap Gaussian (sigma=1.5) as compile-time literals
__device__ __forceinline__ float gw(int t) {
    constexpr float W[11] = {
        0.00102838f, 0.00759876f, 0.03600075f, 0.10936071f, 0.21300558f,
        0.26601173f,
        0.21300558f, 0.10936071f, 0.03600075f, 0.00759876f, 0.00102838f
    };
    return W[t];
}

// Pyramid in (s,d) space: s=x+y, d=x-y, interleaved float2.
__device__ float2 g_pyrA[NIMG * 256 * 256];   // level 1
__device__ float2 g_pyrB[NIMG * 128 * 128];   // level 2
__device__ float2 g_pyrC[NIMG * 64 * 64];     // level 3
__device__ float2 g_pyrD[NIMG * 32 * 32];     // level 4
__device__ double g_acc[5];

__global__ void zero_acc_kernel() {
    if (threadIdx.x < 5) g_acc[threadIdx.x] = 0.0;
}

// One 32x64 SSIM tile in (s,d) space, 512 threads.
// Pass 1: vertical blur of {s,d,s^2,d^2}, 4-row units (592 units).
// Pass 2: horizontal blur, 4 px/thread, q-loop LDS.128; SSIM; reduce.
// wlim: number of valid output columns in this tile (<TC only for L4).
template<bool POOL, bool SD_IN>
__device__ __forceinline__ void ssim_tile(
    const float* __restrict__ X, const float* __restrict__ Y,   // SD_IN=false
    const float2* __restrict__ XY,                              // SD_IN=true
    int H, int W, int tx, int ty, int img, int wlim,
    double* __restrict__ acc, float2* __restrict__ PO)
{
    extern __shared__ __align__(16) char smem_raw[];
    float2* sxy  = (float2*)smem_raw;            // [HTR][SXP]
    float2* hbSD = sxy  + HTR * SXP;             // [TR][SXP]
    float2* hbPQ = hbSD + TR * SXP;              // [TR][SXP]
    float*  wsum = (float*)(hbPQ + TR * SXP);    // [16]

    const int tid  = threadIdx.x;
    const int base = img * H * W;
    const int r0   = ty * TR - R;
    const int c0   = tx * TC - R;

    // ---- load tile + halo (zero padding outside image) ----
    for (int i = tid; i < HTR * HTC; i += 512) {
        int r  = i / HTC, c = i - r * HTC;
        int gr = r0 + r, gc = c0 + c;
        float sv = 0.0f, dv = 0.0f;
        if ((unsigned)gr < (unsigned)H && (unsigned)gc < (unsigned)W) {
            int gi = base + gr * W + gc;
            if (SD_IN) {
                float2 v = XY[gi];
                sv = v.x; dv = v.y;
            } else {
                float xv = X[gi], yv = Y[gi];
                sv = xv + yv; dv = xv - yv;
            }
        }
        sxy[r * SXP + c] = make_float2(sv, dv);
    }
    __syncthreads();

    // ---- fused 2x2 avg-pool of the central 32x64 (next level's input) ----
    if (POOL) {
        int pr = tid >> 5, pc = tid & 31;        // 16 x 32 outputs
        int rr = R + 2 * pr, cc = R + 2 * pc;
        float2 a = sxy[rr * SXP + cc],       b = sxy[rr * SXP + cc + 1];
        float2 c = sxy[(rr + 1) * SXP + cc], d = sxy[(rr + 1) * SXP + cc + 1];
        int Ho = H >> 1, Wo = W >> 1;
        int o  = img * Ho * Wo + (ty * 16 + pr) * Wo + tx * 32 + pc;
        PO[o] = make_float2(0.25f * (a.x + b.x + c.x + d.x),
                            0.25f * (a.y + b.y + c.y + d.y));
    }

    // ---- pass 1: vertical blur, 4 output rows per unit (8*74=592 units) ----
    for (int u = tid; u < HTC * 8; u += 512) {
        int c  = u % HTC;
        int rb = (u / HTC) * 4;
        float aS[4] = {}, aD[4] = {}, aP[4] = {}, aQ[4] = {};
#pragma unroll
        for (int t = 0; t < 14; t++) {
            float2 v = sxy[(rb + t) * SXP + c];
            float s2 = v.x * v.x, d2 = v.y * v.y;
#pragma unroll
            for (int k = 0; k < 4; k++) {
                int tt = t - k;                 // compile-time after unroll
                if (tt >= 0 && tt <= 10) {
                    float w = gw(tt);
                    aS[k] += w * v.x;
                    aD[k] += w * v.y;
                    aP[k] += w * s2;
                    aQ[k] += w * d2;
                }
            }
        }
#pragma unroll
        for (int k = 0; k < 4; k++) {
            hbSD[(rb + k) * SXP + c] = make_float2(aS[k], aD[k]);
            hbPQ[(rb + k) * SXP + c] = make_float2(aP[k], aQ[k]);
        }
    }
    __syncthreads();

    // ---- pass 2: horizontal blur + SSIM, 4 px/thread ----
    const int vr = tid >> 4;          // output row 0..31
    const int vc = (tid & 15) * 4;    // output col group (16B aligned)

    float mS[4] = {}, mD[4] = {}, mP[4] = {}, mQ[4] = {};

    {   // (S, D) stream — 7 x LDS.128, consumed immediately (low regs)
        const float4* p = (const float4*)&hbSD[vr * SXP + vc];
#pragma unroll
        for (int q = 0; q < 7; q++) {
            float4 a = p[q];
#pragma unroll
            for (int k = 0; k < 4; k++) {
                int t0 = 2 * q - k, t1 = 2 * q + 1 - k;
                if (t0 >= 0 && t0 <= 10) { mS[k] += gw(t0) * a.x; mD[k] += gw(t0) * a.y; }
                if (t1 >= 0 && t1 <= 10) { mS[k] += gw(t1) * a.z; mD[k] += gw(t1) * a.w; }
            }
        }
    }
    {   // (P, Q) stream — 7 x LDS.128
        const float4* p = (const float4*)&hbPQ[vr * SXP + vc];
#pragma unroll
        for (int q = 0; q < 7; q++) {
            float4 a = p[q];
#pragma unroll
            for (int k = 0; k < 4; k++) {
                int t0 = 2 * q - k, t1 = 2 * q + 1 - k;
                if (t0 >= 0 && t0 <= 10) { mP[k] += gw(t0) * a.x; mQ[k] += gw(t0) * a.y; }
                if (t1 >= 0 && t1 <= 10) { mP[k] += gw(t1) * a.z; mQ[k] += gw(t1) * a.w; }
            }
        }
    }

    const float C1 = 4.0e-4f;   // (0.01*2)^2
    const float C2 = 3.6e-3f;   // (0.03*2)^2
    float lsum = 0.f;
#pragma unroll
    for (int k = 0; k < 4; k++) {
        if (vc + k < wlim) {
            float S2 = mS[k] * mS[k];
            float D2 = mD[k] * mD[k];
            float sumSq = 0.5f * (S2 + D2);                   // mu1^2 + mu2^2
            float difSq = 0.5f * (S2 - D2);                   // 2*mu1*mu2
            float A1 = difSq + C1;
            float B1 = sumSq + C1;
            float A2 = 0.5f * (mP[k] - mQ[k]) - difSq + C2;   // 2*sig12 + C2
            float B2 = 0.5f * (mP[k] + mQ[k]) - sumSq + C2;   // sig1+sig2 + C2
            lsum += __fdividef(A1 * A2, B1 * B2 + 1e-8f);
        }
    }

    // ---- block reduction -> one double atomic per block ----
#pragma unroll
    for (int o = 16; o > 0; o >>= 1)
        lsum += __shfl_xor_sync(0xFFFFFFFFu, lsum, o);
    if ((tid & 31) == 0) wsum[tid >> 5] = lsum;
    __syncthreads();
    if (tid == 0) {
        float b = 0.f;
#pragma unroll
        for (int i = 0; i < 16; i++) b += wsum[i];
        atomicAdd(acc, (double)b);
    }
}

// Level 0 (512^2), fused pool -> pyrA (256^2, s/d space)
__global__ __launch_bounds__(512, 3) void ssim_l0_kernel(
    const float* __restrict__ X, const float* __restrict__ Y,
    double* __restrict__ acc, float2* __restrict__ PO)
{
    ssim_tile<true, false>(X, Y, nullptr, 512, 512,
                           blockIdx.x, blockIdx.y, blockIdx.z, TC, acc, PO);
}

// Merged tail: all 43 tiles/image of levels 1..4 in one launch.
__global__ __launch_bounds__(512, 3) void ssim_tail_kernel(
    const float2* __restrict__ A, const float2* __restrict__ B,
    const float2* __restrict__ C, const float2* __restrict__ D,
    double* __restrict__ acc)
{
    int bx = blockIdx.x;
    const float2* XY;
    int H, tx, ty, lvl, wlim = TC;
    if (bx < 32)      { lvl = 1; H = 256; tx = bx & 3; ty = bx >> 2;                XY = A; }
    else if (bx < 40) { lvl = 2; H = 128; int b = bx - 32; tx = b & 1; ty = b >> 1; XY = B; }
    else if (bx < 42) { lvl = 3; H = 64;  tx = 0; ty = bx - 40;                     XY = C; }
    else              { lvl = 4; H = 32;  tx = 0; ty = 0; wlim = 32;                XY = D; }
    ssim_tile<false, true>(nullptr, nullptr, XY, H, H, tx, ty, blockIdx.z,
                           wlim, acc + lvl, nullptr);
}

// Local pyramid: each block pools its 64x64 region of A (256^2) down to
// B (128^2), C (64^2), D (32^2) entirely in smem. grid (4,4,NIMG).
__global__ __launch_bounds__(256) void pooltree_kernel(
    const float2* __restrict__ A, float2* __restrict__ B,
    float2* __restrict__ C, float2* __restrict__ D)
{
    __shared__ float2 p1[32][33];
    __shared__ float2 p2[16][17];
    const int tid = threadIdx.x;
    const int img = blockIdx.z;
    const int rx  = blockIdx.x, ry = blockIdx.y;

    const float2* a0 = A + img * 256 * 256;

    // pool A(64x64 region) -> 32x32, 4 outputs/thread
#pragma unroll
    for (int j = 0; j < 4; j++) {
        int o = tid + j * 256;            // 0..1023
        int r = o >> 5, c = o & 31;
        int gr = ry * 64 + 2 * r, gc = rx * 64 + 2 * c;
        float2 a = a0[gr * 256 + gc],       b = a0[gr * 256 + gc + 1];
        float2 e = a0[(gr + 1) * 256 + gc], f = a0[(gr + 1) * 256 + gc + 1];
        float2 pv = make_float2(0.25f * (a.x + b.x + e.x + f.x),
                                0.25f * (a.y + b.y + e.y + f.y));
        int ob = img * 128 * 128 + (ry * 32 + r) * 128 + rx * 32 + c;
        B[ob] = pv;
        p1[r][c] = pv;
    }
    __syncthreads();

    // 32x32 -> 16x16, 1 output/thread
    {
        int r = tid >> 4, c = tid & 15;
        float2 a = p1[2 * r][2 * c],     b = p1[2 * r][2 * c + 1];
        float2 d = p1[2 * r + 1][2 * c], e = p1[2 * r + 1][2 * c + 1];
        float2 pv = make_float2(0.25f * (a.x + b.x + d.x + e.x),
                                0.25f * (a.y + b.y + d.y + e.y));
        int oc = img * 64 * 64 + (ry * 16 + r) * 64 + rx * 16 + c;
        C[oc] = pv;
        p2[r][c] = pv;
    }
    __syncthreads();

    // 16x16 -> 8x8
    if (tid < 64) {
        int r = tid >> 3, c = tid & 7;
        float2 a = p2[2 * r][2 * c],     b = p2[2 * r][2 * c + 1];
        float2 d = p2[2 * r + 1][2 * c], e = p2[2 * r + 1][2 * c + 1];
        int od = img * 32 * 32 + (ry * 8 + r) * 32 + rx * 8 + c;
        D[od] = make_float2(0.25f * (a.x + b.x + d.x + e.x),
                            0.25f * (a.y + b.y + d.y + e.y));
    }
}

__global__ void finish_kernel(float* __restrict__ out) {
    const double w[5] = {0.0448, 0.2856, 0.3001, 0.2363, 0.1333};
    const double wsumv = 1.0001;  // reference normalizes by the weight sum
    double cnt = (double)NIMG * 512.0 * 512.0;
    double m = 0.0;
#pragma unroll
    for (int l = 0; l < 5; l++) {
        m += (w[l] / wsumv) * (g_acc[l] / cnt);
        cnt *= 0.25;
    }
    out[0] = (float)(1.0 - m);
}

extern "C" void kernel_launch(void* const* d_in, const int* in_sizes, int n_in,
                              void* d_out, int out_size)
{
    (void)in_sizes; (void)n_in; (void)out_size;
    const float* pred   = (const float*)d_in[0];
    const float* target = (const float*)d_in[1];
    float* out = (float*)d_out;

    float2 *pA, *pB, *pC, *pD;
    double* acc;
    cudaGetSymbolAddress((void**)&pA, g_pyrA);
    cudaGetSymbolAddress((void**)&pB, g_pyrB);
    cudaGetSymbolAddress((void**)&pC, g_pyrC);
    cudaGetSymbolAddress((void**)&pD, g_pyrD);
    cudaGetSymbolAddress((void**)&acc, g_acc);

    cudaFuncSetAttribute(ssim_l0_kernel,
                         cudaFuncAttributeMaxDynamicSharedMemorySize, SMEM_BYTES);
    cudaFuncSetAttribute(ssim_tail_kernel,
                         cudaFuncAttributeMaxDynamicSharedMemorySize, SMEM_BYTES);

    zero_acc_kernel<<<1, 32>>>();

    // L0: SSIM + fused pool -> A (256^2, s/d space). 8x16 tiles of 64x32.
    ssim_l0_kernel<<<dim3(8, 16, NIMG), 512, SMEM_BYTES>>>(pred, target, acc, pA);

    // Build remaining pyramid locally: A -> B, C, D
    pooltree_kernel<<<dim3(4, 4, NIMG), 256>>>(pA, pB, pC, pD);

    // Levels 1..4 merged into a single launch (43 tiles per image)
    ssim_tail_kernel<<<dim3(43, 1, NIMG), 512, SMEM_BYTES>>>(pA, pB, pC, pD, acc);

    finish_kernel<<<1, 1>>>(out);
}

// round 9
// speedup vs baseline: 1.1522x; 1.0508x over previous
#include <cuda_runtime.h>

#define R     5
#define TILE  32
#define HTR   42         // rows: TILE + 2*5
#define HTC   44         // cols loaded: halo -6..+5 (even base => aligned loads)
#define SXP   46         // sxy row stride in float2 (even => 16B-aligned rows)
#define NIMG  48         // 16 batch * 3 channels

// Normalized 11-tap Gaussian (sigma=1.5) as compile-time literals
__device__ __forceinline__ float gw(int t) {
    constexpr float W[11] = {
        0.00102838f, 0.00759876f, 0.03600075f, 0.10936071f, 0.21300558f,
        0.26601173f,
        0.21300558f, 0.10936071f, 0.03600075f, 0.00759876f, 0.00102838f
    };
    return W[t];
}
// Pass-2 scaled weights: SD stream x 1/sqrt(2), PQ stream x 0.5
__device__ __forceinline__ float gwS(int t) { return gw(t) * 0.70710678118654752f; }
__device__ __forceinline__ float gwP(int t) { return gw(t) * 0.5f; }

// Pyramid in (s,d) space: s=x+y, d=x-y, interleaved float2.
__device__ float2 g_pyrA[NIMG * 256 * 256];   // level 1
__device__ float2 g_pyrB[NIMG * 128 * 128];   // level 2
__device__ float2 g_pyrC[NIMG * 64 * 64];     // level 3
__device__ float2 g_pyrD[NIMG * 32 * 32];     // level 4
__device__ double g_acc[5];

__global__ void zero_acc_kernel() {
    if (threadIdx.x < 5) g_acc[threadIdx.x] = 0.0;
}

// One 32x32 SSIM tile in (s,d) space. R5 balanced structure + aligned
// interior fast-path loads + prescaled pass-2 weights.
template<bool POOL, bool SD_IN>
__device__ __forceinline__ void ssim_tile(
    const float* __restrict__ X, const float* __restrict__ Y,   // SD_IN=false
    const float2* __restrict__ XY,                              // SD_IN=true
    int H, int W, int tx, int ty, int img,
    double* __restrict__ acc, float2* __restrict__ PO)
{
    __shared__ __align__(16) float2 sxy[HTR][SXP];   // (s, d), cols 0..43
    __shared__ __align__(16) float2 hbSD[TILE][44];  // v-blurred (s, d)
    __shared__ __align__(16) float2 hbPQ[TILE][44];  // v-blurred (s^2, d^2)
    __shared__ float wsum[8];

    const int tid  = threadIdx.x;
    const int base = img * H * W;
    const int r0   = ty * TILE - R;       // row halo: -5..+5
    const int c0   = tx * TILE - 6;       // col halo: -6..+5 (even base)

    const bool interior = (r0 >= 0) && (r0 + HTR <= H) && (c0 >= 0) && (c0 + HTC <= W);

    // ---- load tile + halo ----
    if (interior) {
        if (SD_IN) {
            // 42 rows x 22 float4 (2 px each), all aligned
            for (int i = tid; i < HTR * 22; i += 256) {
                int r = i / 22, c4 = i - r * 22;
                const float4* p = (const float4*)(XY + base + (r0 + r) * W + c0) + c4;
                *((float4*)&sxy[r][2 * c4]) = *p;
            }
        } else {
            // 42 rows x 22 float2-pairs from X and Y
            for (int i = tid; i < HTR * 22; i += 256) {
                int r = i / 22, c2 = i - r * 22;
                int gi = base + (r0 + r) * W + c0 + 2 * c2;
                float2 xa = *(const float2*)(X + gi);
                float2 ya = *(const float2*)(Y + gi);
                float4 v;
                v.x = xa.x + ya.x; v.y = xa.x - ya.x;
                v.z = xa.y + ya.y; v.w = xa.y - ya.y;
                *((float4*)&sxy[r][2 * c2]) = v;
            }
        }
    } else {
        for (int i = tid; i < HTR * HTC; i += 256) {
            int r  = i / HTC, c = i - r * HTC;
            int gr = r0 + r, gc = c0 + c;
            float sv = 0.0f, dv = 0.0f;
            if ((unsigned)gr < (unsigned)H && (unsigned)gc < (unsigned)W) {
                int gi = base + gr * W + gc;
                if (SD_IN) {
                    float2 v = XY[gi];
                    sv = v.x; dv = v.y;
                } else {
                    float xv = X[gi], yv = Y[gi];
                    sv = xv + yv; dv = xv - yv;
                }
            }
            sxy[r][c] = make_float2(sv, dv);
        }
    }
    __syncthreads();

    // ---- fused 2x2 avg-pool of the central 32x32 (next level's input) ----
    if (POOL) {
        int pr = tid >> 4, pc = tid & 15;
        int rr = R + 2 * pr, cc = 6 + 2 * pc;
        float2 a = sxy[rr][cc],     b = sxy[rr][cc + 1];
        float2 c = sxy[rr + 1][cc], d = sxy[rr + 1][cc + 1];
        int Ho = H >> 1, Wo = W >> 1;
        int o  = img * Ho * Wo + (ty * 16 + pr) * Wo + tx * 16 + pc;
        PO[o] = make_float2(0.25f * (a.x + b.x + c.x + d.x),
                            0.25f * (a.y + b.y + c.y + d.y));
    }

    // ---- pass 1: vertical blur, 4 output rows per unit (336 units) ----
    // hb col c corresponds to sxy col c+1 (pass 2 needs sxy cols 1..42)
    for (int u = tid; u < 42 * 8; u += 256) {
        int c  = u % 42;
        int rb = (u / 42) * 4;
        float aS[4] = {}, aD[4] = {}, aP[4] = {}, aQ[4] = {};
#pragma unroll
        for (int t = 0; t < 14; t++) {
            float2 v = sxy[rb + t][c + 1];
            float s2 = v.x * v.x, d2 = v.y * v.y;
#pragma unroll
            for (int k = 0; k < 4; k++) {
                int tt = t - k;                 // compile-time after unroll
                if (tt >= 0 && tt <= 10) {
                    float w = gw(tt);
                    aS[k] += w * v.x;
                    aD[k] += w * v.y;
                    aP[k] += w * s2;
                    aQ[k] += w * d2;
                }
            }
        }
#pragma unroll
        for (int k = 0; k < 4; k++) {
            hbSD[rb + k][c] = make_float2(aS[k], aD[k]);
            hbPQ[rb + k][c] = make_float2(aP[k], aQ[k]);
        }
    }
    __syncthreads();

    // ---- pass 2: horizontal blur + SSIM, 4 px/thread ----
    const int vr = tid >> 3;          // output row 0..31
    const int vc = (tid & 7) * 4;     // output col group (16B aligned)

    float mS[4] = {}, mD[4] = {}, mP[4] = {}, mQ[4] = {};

    {   // (S, D) stream — 7 x LDS.128, weights prescaled by 1/sqrt(2)
        float2 v[14];
        const float4* p = (const float4*)&hbSD[vr][vc];
#pragma unroll
        for (int q = 0; q < 7; q++) {
            float4 a = p[q];
            v[2 * q]     = make_float2(a.x, a.y);
            v[2 * q + 1] = make_float2(a.z, a.w);
        }
#pragma unroll
        for (int t = 0; t < 14; t++)
#pragma unroll
            for (int k = 0; k < 4; k++) {
                int tt = t - k;
                if (tt >= 0 && tt <= 10) {
                    mS[k] += gwS(tt) * v[t].x;
                    mD[k] += gwS(tt) * v[t].y;
                }
            }
    }
    {   // (P, Q) stream — 7 x LDS.128, weights prescaled by 0.5
        float2 v[14];
        const float4* p = (const float4*)&hbPQ[vr][vc];
#pragma unroll
        for (int q = 0; q < 7; q++) {
            float4 a = p[q];
            v[2 * q]     = make_float2(a.x, a.y);
            v[2 * q + 1] = make_float2(a.z, a.w);
        }
#pragma unroll
        for (int t = 0; t < 14; t++)
#pragma unroll
            for (int k = 0; k < 4; k++) {
                int tt = t - k;
                if (tt >= 0 && tt <= 10) {
                    mP[k] += gwP(tt) * v[t].x;
                    mQ[k] += gwP(tt) * v[t].y;
                }
            }
    }

    const float C1 = 4.0e-4f;   // (0.01*2)^2
    const float C2 = 3.6e-3f;   // (0.03*2)^2
    float lsum = 0.f;
#pragma unroll
    for (int k = 0; k < 4; k++) {
        float S2 = mS[k] * mS[k];           // = mu-sums scaled: S^2/2
        float D2 = mD[k] * mD[k];           // = D^2/2
        float sumSq = S2 + D2;              // mu1^2 + mu2^2
        float difSq = S2 - D2;              // 2*mu1*mu2
        float A1 = difSq + C1;
        float B1 = sumSq + C1;
        float A2 = (mP[k] - mQ[k]) - difSq + C2;   // 2*sig12 + C2
        float B2 = (mP[k] + mQ[k]) - sumSq + C2;   // sig1+sig2 + C2
        lsum += __fdividef(A1 * A2, B1 * B2 + 1e-8f);
    }

    // ---- block reduction -> one double atomic per block ----
#pragma unroll
    for (int o = 16; o > 0; o >>= 1)
        lsum += __shfl_xor_sync(0xFFFFFFFFu, lsum, o);
    if ((tid & 31) == 0) wsum[tid >> 5] = lsum;
    __syncthreads();
    if (tid == 0) {
        float b = 0.f;
#pragma unroll
        for (int i = 0; i < 8; i++) b += wsum[i];
        atomicAdd(acc, (double)b);
    }
}

// Level 0 (512^2), fused pool -> pyrA (256^2, s/d space)
__global__ __launch_bounds__(256, 5) void ssim_l0_kernel(
    const float* __restrict__ X, const float* __restrict__ Y,
    double* __restrict__ acc, float2* __restrict__ PO)
{
    ssim_tile<true, false>(X, Y, nullptr, 512, 512,
                           blockIdx.x, blockIdx.y, blockIdx.z, acc, PO);
}

// Merged tail: all 85 tiles/image of levels 1..4 in one launch.
__global__ __launch_bounds__(256, 5) void ssim_tail_kernel(
    const float2* __restrict__ A, const float2* __restrict__ B,
    const float2* __restrict__ C, const float2* __restrict__ D,
    double* __restrict__ acc)
{
    int bx = blockIdx.x;
    const float2* XY;
    int H, tx, ty, lvl;
    if (bx < 64)      { lvl = 1; H = 256; tx = bx & 7;  ty = bx >> 3;               XY = A; }
    else if (bx < 80) { lvl = 2; H = 128; int b = bx - 64; tx = b & 3; ty = b >> 2; XY = B; }
    else if (bx < 84) { lvl = 3; H = 64;  int b = bx - 80; tx = b & 1; ty = b >> 1; XY = C; }
    else              { lvl = 4; H = 32;  tx = 0; ty = 0;                           XY = D; }
    ssim_tile<false, true>(nullptr, nullptr, XY, H, H, tx, ty, blockIdx.z,
                           acc + lvl, nullptr);
}

// Local pyramid: each block pools its 64x64 region of A (256^2) down to
// B (128^2), C (64^2), D (32^2) entirely in smem. grid (4,4,NIMG).
__global__ __launch_bounds__(256) void pooltree_kernel(
    const float2* __restrict__ A, float2* __restrict__ B,
    float2* __restrict__ C, float2* __restrict__ D)
{
    __shared__ float2 p1[32][33];
    __shared__ float2 p2[16][17];
    const int tid = threadIdx.x;
    const int img = blockIdx.z;
    const int rx  = blockIdx.x, ry = blockIdx.y;

    const float2* a0 = A + img * 256 * 256;

    // pool A(64x64 region) -> 32x32, 4 outputs/thread
#pragma unroll
    for (int j = 0; j < 4; j++) {
        int o = tid + j * 256;            // 0..1023
        int r = o >> 5, c = o & 31;
        int gr = ry * 64 + 2 * r, gc = rx * 64 + 2 * c;
        float2 a = a0[gr * 256 + gc],       b = a0[gr * 256 + gc + 1];
        float2 e = a0[(gr + 1) * 256 + gc], f = a0[(gr + 1) * 256 + gc + 1];
        float2 pv = make_float2(0.25f * (a.x + b.x + e.x + f.x),
                                0.25f * (a.y + b.y + e.y + f.y));
        int ob = img * 128 * 128 + (ry * 32 + r) * 128 + rx * 32 + c;
        B[ob] = pv;
        p1[r][c] = pv;
    }
    __syncthreads();

    // 32x32 -> 16x16, 1 output/thread
    {
        int r = tid >> 4, c = tid & 15;
        float2 a = p1[2 * r][2 * c],     b = p1[2 * r][2 * c + 1];
        float2 d = p1[2 * r + 1][2 * c], e = p1[2 * r + 1][2 * c + 1];
        float2 pv = make_float2(0.25f * (a.x + b.x + d.x + e.x),
                                0.25f * (a.y + b.y + d.y + e.y));
        int oc = img * 64 * 64 + (ry * 16 + r) * 64 + rx * 16 + c;
        C[oc] = pv;
        p2[r][c] = pv;
    }
    __syncthreads();

    // 16x16 -> 8x8
    if (tid < 64) {
        int r = tid >> 3, c = tid & 7;
        float2 a = p2[2 * r][2 * c],     b = p2[2 * r][2 * c + 1];
        float2 d = p2[2 * r + 1][2 * c], e = p2[2 * r + 1][2 * c + 1];
        int od = img * 32 * 32 + (ry * 8 + r) * 32 + rx * 8 + c;
        D[od] = make_float2(0.25f * (a.x + b.x + d.x + e.x),
                            0.25f * (a.y + b.y + d.y + e.y));
    }
}

__global__ void finish_kernel(float* __restrict__ out) {
    const double w[5] = {0.0448, 0.2856, 0.3001, 0.2363, 0.1333};
    const double wsumv = 1.0001;  // reference normalizes by the weight sum
    double cnt = (double)NIMG * 512.0 * 512.0;
    double m = 0.0;
#pragma unroll
    for (int l = 0; l < 5; l++) {
        m += (w[l] / wsumv) * (g_acc[l] / cnt);
        cnt *= 0.25;
    }
    out[0] = (float)(1.0 - m);
}

extern "C" void kernel_launch(void* const* d_in, const int* in_sizes, int n_in,
                              void* d_out, int out_size)
{
    (void)in_sizes; (void)n_in; (void)out_size;
    const float* pred   = (const float*)d_in[0];
    const float* target = (const float*)d_in[1];
    float* out = (float*)d_out;

    float2 *pA, *pB, *pC, *pD;
    double* acc;
    cudaGetSymbolAddress((void**)&pA, g_pyrA);
    cudaGetSymbolAddress((void**)&pB, g_pyrB);
    cudaGetSymbolAddress((void**)&pC, g_pyrC);
    cudaGetSymbolAddress((void**)&pD, g_pyrD);
    cudaGetSymbolAddress((void**)&acc, g_acc);

    zero_acc_kernel<<<1, 32>>>();

    // L0: SSIM + fused pool -> A (256^2, s/d space)
    ssim_l0_kernel<<<dim3(16, 16, NIMG), 256>>>(pred, target, acc, pA);

    // Build remaining pyramid locally: A -> B, C, D
    pooltree_kernel<<<dim3(4, 4, NIMG), 256>>>(pA, pB, pC, pD);

    // Levels 1..4 merged into a single launch (85 tiles per image)
    ssim_tail_kernel<<<dim3(85, 1, NIMG), 256>>>(pA, pB, pC, pD, acc);

    finish_kernel<<<1, 1>>>(out);
}

// round 10
// speedup vs baseline: 1.1715x; 1.0167x over previous
#include <cuda_runtime.h>

#define R     5
#define TILE  32
#define HTR   42         // rows: TILE + 2*5
#define HTC   44         // cols loaded: halo -6..+5 (even base => aligned loads)
#define SXP   44         // sxy row stride in float2 (16B-aligned rows)
#define NIMG  48         // 16 batch * 3 channels

// Normalized 11-tap Gaussian (sigma=1.5) as compile-time literals
__device__ __forceinline__ float gw(int t) {
    constexpr float W[11] = {
        0.00102838f, 0.00759876f, 0.03600075f, 0.10936071f, 0.21300558f,
        0.26601173f,
        0.21300558f, 0.10936071f, 0.03600075f, 0.00759876f, 0.00102838f
    };
    return W[t];
}
// Pass-2 scaled weights: SD stream x 1/sqrt(2), PQ stream x 0.5
__device__ __forceinline__ float gwS(int t) { return gw(t) * 0.70710678118654752f; }
__device__ __forceinline__ float gwP(int t) { return gw(t) * 0.5f; }

// Pyramid in (s,d) space: s=x+y, d=x-y, interleaved float2.
__device__ float2 g_pyrA[NIMG * 256 * 256];   // level 1
__device__ float2 g_pyrB[NIMG * 128 * 128];   // level 2
__device__ float2 g_pyrC[NIMG * 64 * 64];     // level 3
__device__ float2 g_pyrD[NIMG * 32 * 32];     // level 4
__device__ double g_acc[5];                    // zero-init; finish re-zeroes

// One 32x32 SSIM tile in (s,d) space. Balanced 256-thread structure,
// aligned interior fast-path loads, prescaled pass-2 weights.
// POOL=true additionally emits this tile's patches of ALL pyramid levels
// (A:16x16, B:8x8, C:4x4, D:2x2), reusing hb smem as scratch at the end.
template<bool POOL, bool SD_IN>
__device__ __forceinline__ void ssim_tile(
    const float* __restrict__ X, const float* __restrict__ Y,   // SD_IN=false
    const float2* __restrict__ XY,                              // SD_IN=true
    int H, int W, int tx, int ty, int img,
    double* __restrict__ acc,
    float2* __restrict__ PA, float2* __restrict__ PB,
    float2* __restrict__ PC, float2* __restrict__ PD)
{
    __shared__ __align__(16) float2 sxy[HTR][SXP];   // (s, d), cols 0..43
    __shared__ __align__(16) float2 hbSD[TILE][44];  // v-blurred (s, d)
    __shared__ __align__(16) float2 hbPQ[TILE][44];  // v-blurred (s^2, d^2)
    __shared__ float wsum[8];

    const int tid  = threadIdx.x;
    const int base = img * H * W;
    const int r0   = ty * TILE - R;       // row halo: -5..+5
    const int c0   = tx * TILE - 6;       // col halo: -6..+5 (even base)

    const bool interior = (r0 >= 0) && (r0 + HTR <= H) && (c0 >= 0) && (c0 + HTC <= W);

    // ---- load tile + halo ----
    if (interior) {
        if (SD_IN) {
            for (int i = tid; i < HTR * 22; i += 256) {
                int r = i / 22, c4 = i - r * 22;
                const float4* p = (const float4*)(XY + base + (r0 + r) * W + c0) + c4;
                *((float4*)&sxy[r][2 * c4]) = *p;
            }
        } else {
            for (int i = tid; i < HTR * 22; i += 256) {
                int r = i / 22, c2 = i - r * 22;
                int gi = base + (r0 + r) * W + c0 + 2 * c2;
                float2 xa = *(const float2*)(X + gi);
                float2 ya = *(const float2*)(Y + gi);
                float4 v;
                v.x = xa.x + ya.x; v.y = xa.x - ya.x;
                v.z = xa.y + ya.y; v.w = xa.y - ya.y;
                *((float4*)&sxy[r][2 * c2]) = v;
            }
        }
    } else {
        for (int i = tid; i < HTR * HTC; i += 256) {
            int r  = i / HTC, c = i - r * HTC;
            int gr = r0 + r, gc = c0 + c;
            float sv = 0.0f, dv = 0.0f;
            if ((unsigned)gr < (unsigned)H && (unsigned)gc < (unsigned)W) {
                int gi = base + gr * W + gc;
                if (SD_IN) {
                    float2 v = XY[gi];
                    sv = v.x; dv = v.y;
                } else {
                    float xv = X[gi], yv = Y[gi];
                    sv = xv + yv; dv = xv - yv;
                }
            }
            sxy[r][c] = make_float2(sv, dv);
        }
    }
    __syncthreads();

    // ---- pass 1: vertical blur, 4 output rows per unit (336 units) ----
    // hb col c corresponds to sxy col c+1 (pass 2 needs sxy cols 1..42)
    for (int u = tid; u < 42 * 8; u += 256) {
        int c  = u % 42;
        int rb = (u / 42) * 4;
        float aS[4] = {}, aD[4] = {}, aP[4] = {}, aQ[4] = {};
#pragma unroll
        for (int t = 0; t < 14; t++) {
            float2 v = sxy[rb + t][c + 1];
            float s2 = v.x * v.x, d2 = v.y * v.y;
#pragma unroll
            for (int k = 0; k < 4; k++) {
                int tt = t - k;                 // compile-time after unroll
                if (tt >= 0 && tt <= 10) {
                    float w = gw(tt);
                    aS[k] += w * v.x;
                    aD[k] += w * v.y;
                    aP[k] += w * s2;
                    aQ[k] += w * d2;
                }
            }
        }
#pragma unroll
        for (int k = 0; k < 4; k++) {
            hbSD[rb + k][c] = make_float2(aS[k], aD[k]);
            hbPQ[rb + k][c] = make_float2(aP[k], aQ[k]);
        }
    }
    __syncthreads();

    // ---- pass 2: horizontal blur + SSIM, 4 px/thread ----
    const int vr = tid >> 3;          // output row 0..31
    const int vc = (tid & 7) * 4;     // output col group (16B aligned)

    float mS[4] = {}, mD[4] = {}, mP[4] = {}, mQ[4] = {};

    {   // (S, D) stream — 7 x LDS.128, weights prescaled by 1/sqrt(2)
        float2 v[14];
        const float4* p = (const float4*)&hbSD[vr][vc];
#pragma unroll
        for (int q = 0; q < 7; q++) {
            float4 a = p[q];
            v[2 * q]     = make_float2(a.x, a.y);
            v[2 * q + 1] = make_float2(a.z, a.w);
        }
#pragma unroll
        for (int t = 0; t < 14; t++)
#pragma unroll
            for (int k = 0; k < 4; k++) {
                int tt = t - k;
                if (tt >= 0 && tt <= 10) {
                    mS[k] += gwS(tt) * v[t].x;
                    mD[k] += gwS(tt) * v[t].y;
                }
            }
    }
    {   // (P, Q) stream — 7 x LDS.128, weights prescaled by 0.5
        float2 v[14];
        const float4* p = (const float4*)&hbPQ[vr][vc];
#pragma unroll
        for (int q = 0; q < 7; q++) {
            float4 a = p[q];
            v[2 * q]     = make_float2(a.x, a.y);
            v[2 * q + 1] = make_float2(a.z, a.w);
        }
#pragma unroll
        for (int t = 0; t < 14; t++)
#pragma unroll
            for (int k = 0; k < 4; k++) {
                int tt = t - k;
                if (tt >= 0 && tt <= 10) {
                    mP[k] += gwP(tt) * v[t].x;
                    mQ[k] += gwP(tt) * v[t].y;
                }
            }
    }

    const float C1 = 4.0e-4f;   // (0.01*2)^2
    const float C2 = 3.6e-3f;   // (0.03*2)^2
    float lsum = 0.f;
#pragma unroll
    for (int k = 0; k < 4; k++) {
        float S2 = mS[k] * mS[k];           // S^2/2
        float D2 = mD[k] * mD[k];           // D^2/2
        float sumSq = S2 + D2;              // mu1^2 + mu2^2
        float difSq = S2 - D2;              // 2*mu1*mu2
        float A1 = difSq + C1;
        float B1 = sumSq + C1;
        float A2 = (mP[k] - mQ[k]) - difSq + C2;   // 2*sig12 + C2
        float B2 = (mP[k] + mQ[k]) - sumSq + C2;   // sig1+sig2 + C2
        lsum += __fdividef(A1 * A2, B1 * B2 + 1e-8f);
    }

    // ---- block reduction -> one double atomic per block ----
#pragma unroll
    for (int o = 16; o > 0; o >>= 1)
        lsum += __shfl_xor_sync(0xFFFFFFFFu, lsum, o);
    if ((tid & 31) == 0) wsum[tid >> 5] = lsum;
    __syncthreads();          // hb arrays fully consumed beyond this point
    if (tid == 0) {
        float b = 0.f;
#pragma unroll
        for (int i = 0; i < 8; i++) b += wsum[i];
        atomicAdd(acc, (double)b);
    }

    // ---- fused full pyramid emission (L0 only): A, B, C, D patches ----
    if (POOL) {
        float2* bufA = &hbSD[0][0];       // 16x16 scratch (256 float2)
        float2* bufB = &hbPQ[0][0];       // 8x8 scratch
        float2* bufC = &hbSD[8][0];       // 4x4 scratch (past bufA's 256)

        {   // input(central 32x32) -> A 16x16
            int pr = tid >> 4, pc = tid & 15;
            int rr = R + 2 * pr, cc = 6 + 2 * pc;
            float2 a = sxy[rr][cc],     b = sxy[rr][cc + 1];
            float2 c = sxy[rr + 1][cc], d = sxy[rr + 1][cc + 1];
            float2 av = make_float2(0.25f * (a.x + b.x + c.x + d.x),
                                    0.25f * (a.y + b.y + c.y + d.y));
            PA[img * 256 * 256 + (ty * 16 + pr) * 256 + tx * 16 + pc] = av;
            bufA[pr * 16 + pc] = av;
        }
        __syncthreads();
        if (tid < 64) {   // A -> B 8x8
            int r = tid >> 3, c = tid & 7;
            float2 a = bufA[(2 * r) * 16 + 2 * c],     b = bufA[(2 * r) * 16 + 2 * c + 1];
            float2 d = bufA[(2 * r + 1) * 16 + 2 * c], e = bufA[(2 * r + 1) * 16 + 2 * c + 1];
            float2 bv = make_float2(0.25f * (a.x + b.x + d.x + e.x),
                                    0.25f * (a.y + b.y + d.y + e.y));
            PB[img * 128 * 128 + (ty * 8 + r) * 128 + tx * 8 + c] = bv;
            bufB[r * 8 + c] = bv;
        }
        __syncthreads();
        if (tid < 16) {   // B -> C 4x4
            int r = tid >> 2, c = tid & 3;
            float2 a = bufB[(2 * r) * 8 + 2 * c],     b = bufB[(2 * r) * 8 + 2 * c + 1];
            float2 d = bufB[(2 * r + 1) * 8 + 2 * c], e = bufB[(2 * r + 1) * 8 + 2 * c + 1];
            float2 cv = make_float2(0.25f * (a.x + b.x + d.x + e.x),
                                    0.25f * (a.y + b.y + d.y + e.y));
            PC[img * 64 * 64 + (ty * 4 + r) * 64 + tx * 4 + c] = cv;
            bufC[r * 4 + c] = cv;
        }
        __syncthreads();
        if (tid < 4) {    // C -> D 2x2
            int r = tid >> 1, c = tid & 1;
            float2 a = bufC[(2 * r) * 4 + 2 * c],     b = bufC[(2 * r) * 4 + 2 * c + 1];
            float2 d = bufC[(2 * r + 1) * 4 + 2 * c], e = bufC[(2 * r + 1) * 4 + 2 * c + 1];
            PD[img * 32 * 32 + (ty * 2 + r) * 32 + tx * 2 + c] =
                make_float2(0.25f * (a.x + b.x + d.x + e.x),
                            0.25f * (a.y + b.y + d.y + e.y));
        }
    }
}

// Level 0 (512^2): SSIM + full pyramid emission.
__global__ __launch_bounds__(256, 6) void ssim_l0_kernel(
    const float* __restrict__ X, const float* __restrict__ Y,
    double* __restrict__ acc,
    float2* __restrict__ PA, float2* __restrict__ PB,
    float2* __restrict__ PC, float2* __restrict__ PD)
{
    ssim_tile<true, false>(X, Y, nullptr, 512, 512,
                           blockIdx.x, blockIdx.y, blockIdx.z, acc,
                           PA, PB, PC, PD);
}

// Merged tail: all 85 tiles/image of levels 1..4 in one launch.
__global__ __launch_bounds__(256, 6) void ssim_tail_kernel(
    const float2* __restrict__ A, const float2* __restrict__ B,
    const float2* __restrict__ C, const float2* __restrict__ D,
    double* __restrict__ acc)
{
    int bx = blockIdx.x;
    const float2* XY;
    int H, tx, ty, lvl;
    if (bx < 64)      { lvl = 1; H = 256; tx = bx & 7;  ty = bx >> 3;               XY = A; }
    else if (bx < 80) { lvl = 2; H = 128; int b = bx - 64; tx = b & 3; ty = b >> 2; XY = B; }
    else if (bx < 84) { lvl = 3; H = 64;  int b = bx - 80; tx = b & 1; ty = b >> 1; XY = C; }
    else              { lvl = 4; H = 32;  tx = 0; ty = 0;                           XY = D; }
    ssim_tile<false, true>(nullptr, nullptr, XY, H, H, tx, ty, blockIdx.z,
                           acc + lvl, nullptr, nullptr, nullptr, nullptr);
}

__global__ void finish_kernel(float* __restrict__ out) {
    const double w[5] = {0.0448, 0.2856, 0.3001, 0.2363, 0.1333};
    const double wsumv = 1.0001;  // reference normalizes by the weight sum
    double cnt = (double)NIMG * 512.0 * 512.0;
    double m = 0.0;
#pragma unroll
    for (int l = 0; l < 5; l++) {
        m += (w[l] / wsumv) * (g_acc[l] / cnt);
        cnt *= 0.25;
        g_acc[l] = 0.0;   // restore invariant for next graph replay
    }
    out[0] = (float)(1.0 - m);
}

extern "C" void kernel_launch(void* const* d_in, const int* in_sizes, int n_in,
                              void* d_out, int out_size)
{
    (void)in_sizes; (void)n_in; (void)out_size;
    const float* pred   = (const float*)d_in[0];
    const float* target = (const float*)d_in[1];
    float* out = (float*)d_out;

    float2 *pA, *pB, *pC, *pD;
    double* acc;
    cudaGetSymbolAddress((void**)&pA, g_pyrA);
    cudaGetSymbolAddress((void**)&pB, g_pyrB);
    cudaGetSymbolAddress((void**)&pC, g_pyrC);
    cudaGetSymbolAddress((void**)&pD, g_pyrD);
    cudaGetSymbolAddress((void**)&acc, g_acc);

    // L0: SSIM + full pyramid emission (A, B, C, D)
    ssim_l0_kernel<<<dim3(16, 16, NIMG), 256>>>(pred, target, acc, pA, pB, pC, pD);

    // Levels 1..4 merged into a single launch (85 tiles per image)
    ssim_tail_kernel<<<dim3(85, 1, NIMG), 256>>>(pA, pB, pC, pD, acc);

    finish_kernel<<<1, 1>>>(out);
}

// round 12
// speedup vs baseline: 1.6511x; 1.4094x over previous
#include <cuda_runtime.h>
#include <cuda_fp16.h>

#define R     5
#define TILE  32
#define HTR   42         // rows: TILE + 2*5
#define HTC   48         // cols loaded: halo -8..+7 (16B-aligned everywhere)
#define SXP   48         // sxy row stride in half2 (192B, 16B multiple)
#define HBP   44         // hb row stride in half2 (176B, 16B multiple)
#define NIMG  48         // 16 batch * 3 channels

// ---- compile-time float -> half(RN-ish) converter, duplicated to half2 bits ----
__host__ __device__ constexpr unsigned short f2h_rn(double x) {
    int e = 0;
    double m = x;
    while (m < 1.0)  { m *= 2.0; e--; }
    while (m >= 2.0) { m *= 0.5; e++; }
    int mant = (int)((m - 1.0) * 1024.0 + 0.5);
    int E = e + 15;
    if (mant == 1024) { mant = 0; E += 1; }
    return (unsigned short)((E << 10) | mant);
}
struct HTab { unsigned v[11]; };
__host__ __device__ constexpr HTab make_tab(double s) {
    HTab t{};
    const double w[11] = {
        0.0010283792, 0.0075987573, 0.0360007521, 0.1093607103, 0.2130055812,
        0.2660117310,
        0.2130055812, 0.1093607103, 0.0360007521, 0.0075987573, 0.0010283792 };
    for (int i = 0; i < 11; i++)
        t.v[i] = (unsigned)f2h_rn(w[i] * s) * 0x10001u;
    return t;
}
// Device accessors: local constexpr tables fold to immediates after unroll.
__device__ __forceinline__ unsigned wh1u(int t) {
    constexpr HTab T = make_tab(1.0);                   // pass-1 weights
    return T.v[t];
}
__device__ __forceinline__ unsigned whsu(int t) {
    constexpr HTab T = make_tab(0.70710678118654752);   // pass-2 (S,D): x 1/sqrt(2)
    return T.v[t];
}
__device__ __forceinline__ unsigned whpu(int t) {
    constexpr HTab T = make_tab(0.5);                   // pass-2 (P,Q): x 0.5
    return T.v[t];
}

__device__ __forceinline__ __half2 h2c(unsigned u) {
    __half2_raw r;
    r.x = (unsigned short)(u & 0xFFFFu);
    r.y = (unsigned short)(u >> 16);
    return r;
}
__device__ __forceinline__ __half2 h2zero() { return h2c(0u); }

// Pyramid in (s,d) half2 space.
__device__ __half2 g_pyrA[NIMG * 256 * 256];   // level 1
__device__ __half2 g_pyrB[NIMG * 128 * 128];   // level 2
__device__ __half2 g_pyrC[NIMG * 64 * 64];     // level 3
__device__ __half2 g_pyrD[NIMG * 32 * 32];     // level 4
__device__ double  g_acc[5];                    // zero-init; finish re-zeroes

// One 32x32 SSIM tile, fp16 packed (s,d) math.
template<bool POOL, bool SD_IN>
__device__ __forceinline__ void ssim_tile(
    const float* __restrict__ X, const float* __restrict__ Y,     // SD_IN=false
    const __half2* __restrict__ XY,                               // SD_IN=true
    int H, int W, int tx, int ty, int img,
    double* __restrict__ acc,
    __half2* __restrict__ PA, __half2* __restrict__ PB,
    __half2* __restrict__ PC, __half2* __restrict__ PD)
{
    __shared__ __align__(16) __half2 sxy[HTR][SXP];   // (s, d)
    __shared__ __align__(16) __half2 hbSD[TILE][HBP]; // v-blurred (s, d)
    __shared__ __align__(16) __half2 hbPQ[TILE][HBP]; // v-blurred (s^2, d^2)
    __shared__ float wsum[8];

    const int tid  = threadIdx.x;
    const int base = img * H * W;
    const int r0   = ty * TILE - R;       // row halo: -5..+5
    const int c0   = tx * TILE - 8;       // col halo: -8..+7 (16B-aligned base)

    const bool interior = (r0 >= 0) && (r0 + HTR <= H) && (c0 >= 0) && (c0 + HTC <= W);

    // ---- load tile + halo ----
    if (interior) {
        if (SD_IN) {
            // 42 rows x 12 float4 (4 half2 = 4 px each), all aligned
            for (int i = tid; i < HTR * 12; i += 256) {
                int r = i / 12, c4 = i - r * 12;
                const float4* p = (const float4*)(XY + base + (r0 + r) * W + c0) + c4;
                *(float4*)&sxy[r][4 * c4] = *p;
            }
        } else {
            // 42 rows x 12 float4-of-x + float4-of-y -> 4 half2
            for (int i = tid; i < HTR * 12; i += 256) {
                int r = i / 12, c4 = i - r * 12;
                int gi = base + (r0 + r) * W + c0 + 4 * c4;
                float4 xa = *(const float4*)(X + gi);
                float4 ya = *(const float4*)(Y + gi);
                __half2 h0 = __floats2half2_rn(xa.x + ya.x, xa.x - ya.x);
                __half2 h1 = __floats2half2_rn(xa.y + ya.y, xa.y - ya.y);
                __half2 h2 = __floats2half2_rn(xa.z + ya.z, xa.z - ya.z);
                __half2 h3 = __floats2half2_rn(xa.w + ya.w, xa.w - ya.w);
                uint4 u;
                u.x = *(unsigned*)&h0; u.y = *(unsigned*)&h1;
                u.z = *(unsigned*)&h2; u.w = *(unsigned*)&h3;
                *(uint4*)&sxy[r][4 * c4] = u;
            }
        }
    } else {
        for (int i = tid; i < HTR * HTC; i += 256) {
            int r  = i / HTC, c = i - r * HTC;
            int gr = r0 + r, gc = c0 + c;
            __half2 hv = h2zero();
            if ((unsigned)gr < (unsigned)H && (unsigned)gc < (unsigned)W) {
                int gi = base + gr * W + gc;
                if (SD_IN) {
                    hv = XY[gi];
                } else {
                    float xv = X[gi], yv = Y[gi];
                    hv = __floats2half2_rn(xv + yv, xv - yv);
                }
            }
            sxy[r][c] = hv;
        }
    }
    __syncthreads();

    // ---- pass 1: vertical blur, 4 output rows per unit (336 units) ----
    // hb col c corresponds to sxy col c+3 (image col = tilebase + c - 5)
    for (int u = tid; u < 42 * 8; u += 256) {
        int c  = u % 42;
        int rb = (u / 42) * 4;
        __half2 aSD[4], aPQ[4];
#pragma unroll
        for (int k = 0; k < 4; k++) { aSD[k] = h2zero(); aPQ[k] = h2zero(); }
#pragma unroll
        for (int t = 0; t < 14; t++) {
            __half2 v  = sxy[rb + t][c + 3];
            __half2 v2 = __hmul2(v, v);
#pragma unroll
            for (int k = 0; k < 4; k++) {
                int tt = t - k;                 // compile-time after unroll
                if (tt >= 0 && tt <= 10) {
                    aSD[k] = __hfma2(h2c(wh1u(tt)), v,  aSD[k]);
                    aPQ[k] = __hfma2(h2c(wh1u(tt)), v2, aPQ[k]);
                }
            }
        }
#pragma unroll
        for (int k = 0; k < 4; k++) {
            hbSD[rb + k][c] = aSD[k];
            hbPQ[rb + k][c] = aPQ[k];
        }
    }
    __syncthreads();

    // ---- pass 2: horizontal blur + SSIM, 4 px/thread ----
    const int vr = tid >> 3;          // output row 0..31
    const int vc = (tid & 7) * 4;     // output col group (16B aligned)

    __half2 mSD[4], mPQ[4];
#pragma unroll
    for (int k = 0; k < 4; k++) { mSD[k] = h2zero(); mPQ[k] = h2zero(); }

    {   // (S, D) stream — 4 x LDS.128 covering 16 taps (14 used)
        __half2 vb[16];
        const uint4* p = (const uint4*)&hbSD[vr][vc];
#pragma unroll
        for (int q = 0; q < 4; q++) {
            uint4 a = p[q];
            vb[4 * q + 0] = h2c(a.x); vb[4 * q + 1] = h2c(a.y);
            vb[4 * q + 2] = h2c(a.z); vb[4 * q + 3] = h2c(a.w);
        }
#pragma unroll
        for (int t = 0; t < 14; t++)
#pragma unroll
            for (int k = 0; k < 4; k++) {
                int tt = t - k;
                if (tt >= 0 && tt <= 10)
                    mSD[k] = __hfma2(h2c(whsu(tt)), vb[t], mSD[k]);
            }
    }
    {   // (P, Q) stream — 4 x LDS.128
        __half2 vb[16];
        const uint4* p = (const uint4*)&hbPQ[vr][vc];
#pragma unroll
        for (int q = 0; q < 4; q++) {
            uint4 a = p[q];
            vb[4 * q + 0] = h2c(a.x); vb[4 * q + 1] = h2c(a.y);
            vb[4 * q + 2] = h2c(a.z); vb[4 * q + 3] = h2c(a.w);
        }
#pragma unroll
        for (int t = 0; t < 14; t++)
#pragma unroll
            for (int k = 0; k < 4; k++) {
                int tt = t - k;
                if (tt >= 0 && tt <= 10)
                    mPQ[k] = __hfma2(h2c(whpu(tt)), vb[t], mPQ[k]);
            }
    }

    const float C1 = 4.0e-4f;   // (0.01*2)^2
    const float C2 = 3.6e-3f;   // (0.03*2)^2
    float lsum = 0.f;
#pragma unroll
    for (int k = 0; k < 4; k++) {
        float2 sd = __half22float2(mSD[k]);   // (S/sqrt2, D/sqrt2)
        float2 pq = __half22float2(mPQ[k]);   // (P/2, Q/2)
        float S2 = sd.x * sd.x;               // S^2/2
        float D2 = sd.y * sd.y;               // D^2/2
        float sumSq = S2 + D2;                // mu1^2 + mu2^2
        float difSq = S2 - D2;                // 2*mu1*mu2
        float A1 = difSq + C1;
        float B1 = sumSq + C1;
        float A2 = (pq.x - pq.y) - difSq + C2;   // 2*sig12 + C2
        float B2 = (pq.x + pq.y) - sumSq + C2;   // sig1+sig2 + C2
        lsum += __fdividef(A1 * A2, B1 * B2 + 1e-8f);
    }

    // ---- block reduction -> one double atomic per block ----
#pragma unroll
    for (int o = 16; o > 0; o >>= 1)
        lsum += __shfl_xor_sync(0xFFFFFFFFu, lsum, o);
    if ((tid & 31) == 0) wsum[tid >> 5] = lsum;
    __syncthreads();          // hb arrays fully consumed beyond this point
    if (tid == 0) {
        float b = 0.f;
#pragma unroll
        for (int i = 0; i < 8; i++) b += wsum[i];
        atomicAdd(acc, (double)b);
    }

    // ---- fused full pyramid emission (L0 only): A, B, C, D patches ----
    if (POOL) {
        __half2* bufA = &hbSD[0][0];       // 16x16 scratch (256 half2)
        __half2* bufB = &hbPQ[0][0];       // 8x8 scratch
        __half2* bufC = &hbSD[8][0];       // 4x4 scratch (past bufA's 256)

        {   // input(central 32x32, sxy cols 8..39) -> A 16x16
            int pr = tid >> 4, pc = tid & 15;
            int rr = R + 2 * pr, cc = 8 + 2 * pc;
            float2 a = __half22float2(sxy[rr][cc]);
            float2 b = __half22float2(sxy[rr][cc + 1]);
            float2 c = __half22float2(sxy[rr + 1][cc]);
            float2 d = __half22float2(sxy[rr + 1][cc + 1]);
            __half2 av = __floats2half2_rn(0.25f * (a.x + b.x + c.x + d.x),
                                           0.25f * (a.y + b.y + c.y + d.y));
            PA[img * 256 * 256 + (ty * 16 + pr) * 256 + tx * 16 + pc] = av;
            bufA[pr * 16 + pc] = av;
        }
        __syncthreads();
        if (tid < 64) {   // A -> B 8x8
            int r = tid >> 3, c = tid & 7;
            float2 a = __half22float2(bufA[(2 * r) * 16 + 2 * c]);
            float2 b = __half22float2(bufA[(2 * r) * 16 + 2 * c + 1]);
            float2 d = __half22float2(bufA[(2 * r + 1) * 16 + 2 * c]);
            float2 e = __half22float2(bufA[(2 * r + 1) * 16 + 2 * c + 1]);
            __half2 bv = __floats2half2_rn(0.25f * (a.x + b.x + d.x + e.x),
                                           0.25f * (a.y + b.y + d.y + e.y));
            PB[img * 128 * 128 + (ty * 8 + r) * 128 + tx * 8 + c] = bv;
            bufB[r * 8 + c] = bv;
        }
        __syncthreads();
        if (tid < 16) {   // B -> C 4x4
            int r = tid >> 2, c = tid & 3;
            float2 a = __half22float2(bufB[(2 * r) * 8 + 2 * c]);
            float2 b = __half22float2(bufB[(2 * r) * 8 + 2 * c + 1]);
            float2 d = __half22float2(bufB[(2 * r + 1) * 8 + 2 * c]);
            float2 e = __half22float2(bufB[(2 * r + 1) * 8 + 2 * c + 1]);
            __half2 cv = __floats2half2_rn(0.25f * (a.x + b.x + d.x + e.x),
                                           0.25f * (a.y + b.y + d.y + e.y));
            PC[img * 64 * 64 + (ty * 4 + r) * 64 + tx * 4 + c] = cv;
            bufC[r * 4 + c] = cv;
        }
        __syncthreads();
        if (tid < 4) {    // C -> D 2x2
            int r = tid >> 1, c = tid & 1;
            float2 a = __half22float2(bufC[(2 * r) * 4 + 2 * c]);
            float2 b = __half22float2(bufC[(2 * r) * 4 + 2 * c + 1]);
            float2 d = __half22float2(bufC[(2 * r + 1) * 4 + 2 * c]);
            float2 e = __half22float2(bufC[(2 * r + 1) * 4 + 2 * c + 1]);
            PD[img * 32 * 32 + (ty * 2 + r) * 32 + tx * 2 + c] =
                __floats2half2_rn(0.25f * (a.x + b.x + d.x + e.x),
                                  0.25f * (a.y + b.y + d.y + e.y));
        }
    }
}

// Level 0 (512^2): SSIM + full pyramid emission.
__global__ __launch_bounds__(256, 6) void ssim_l0_kernel(
    const float* __restrict__ X, const float* __restrict__ Y,
    double* __restrict__ acc,
    __half2* __restrict__ PA, __half2* __restrict__ PB,
    __half2* __restrict__ PC, __half2* __restrict__ PD)
{
    ssim_tile<true, false>(X, Y, nullptr, 512, 512,
                           blockIdx.x, blockIdx.y, blockIdx.z, acc,
                           PA, PB, PC, PD);
}

// Merged tail: all 85 tiles/image of levels 1..4 in one launch.
__global__ __launch_bounds__(256, 6) void ssim_tail_kernel(
    const __half2* __restrict__ A, const __half2* __restrict__ B,
    const __half2* __restrict__ C, const __half2* __restrict__ D,
    double* __restrict__ acc)
{
    int bx = blockIdx.x;
    const __half2* XY;
    int H, tx, ty, lvl;
    if (bx < 64)      { lvl = 1; H = 256; tx = bx & 7;  ty = bx >> 3;               XY = A; }
    else if (bx < 80) { lvl = 2; H = 128; int b = bx - 64; tx = b & 3; ty = b >> 2; XY = B; }
    else if (bx < 84) { lvl = 3; H = 64;  int b = bx - 80; tx = b & 1; ty = b >> 1; XY = C; }
    else              { lvl = 4; H = 32;  tx = 0; ty = 0;                           XY = D; }
    ssim_tile<false, true>(nullptr, nullptr, XY, H, H, tx, ty, blockIdx.z,
                           acc + lvl, nullptr, nullptr, nullptr, nullptr);
}

__global__ void finish_kernel(float* __restrict__ out) {
    const double w[5] = {0.0448, 0.2856, 0.3001, 0.2363, 0.1333};
    const double wsumv = 1.0001;  // reference normalizes by the weight sum
    double cnt = (double)NIMG * 512.0 * 512.0;
    double m = 0.0;
#pragma unroll
    for (int l = 0; l < 5; l++) {
        m += (w[l] / wsumv) * (g_acc[l] / cnt);
        cnt *= 0.25;
        g_acc[l] = 0.0;   // restore invariant for next graph replay
    }
    out[0] = (float)(1.0 - m);
}

extern "C" void kernel_launch(void* const* d_in, const int* in_sizes, int n_in,
                              void* d_out, int out_size)
{
    (void)in_sizes; (void)n_in; (void)out_size;
    const float* pred   = (const float*)d_in[0];
    const float* target = (const float*)d_in[1];
    float* out = (float*)d_out;

    __half2 *pA, *pB, *pC, *pD;
    double* acc;
    cudaGetSymbolAddress((void**)&pA, g_pyrA);
    cudaGetSymbolAddress((void**)&pB, g_pyrB);
    cudaGetSymbolAddress((void**)&pC, g_pyrC);
    cudaGetSymbolAddress((void**)&pD, g_pyrD);
    cudaGetSymbolAddress((void**)&acc, g_acc);

    // L0: SSIM + full pyramid emission (A, B, C, D)
    ssim_l0_kernel<<<dim3(16, 16, NIMG), 256>>>(pred, target, acc, pA, pB, pC, pD);

    // Levels 1..4 merged into a single launch (85 tiles per image)
    ssim_tail_kernel<<<dim3(85, 1, NIMG), 256>>>(pA, pB, pC, pD, acc);

    finish_kernel<<<1, 1>>>(out);
}